// round 10
// baseline (speedup 1.0000x reference)
#include <cuda_runtime.h>

// CLIP_AD pooling: patch_tokens [B=512, 225, D=896] f32 -> out [B, 366, 896]:
//   groups   0..168 : mean over 3x3 sliding windows on 15x15 grid (13x13)
//   groups 169..364 : mean over 2x2 sliding windows (14x14)
//   group      365  : mean over all 225 tokens
//
// R9: R8 base (CHUNK=64, TPB=512, cp.async staging, __stcs stores; 161.86us).
// Changes: (1) input reads carry an L2::evict_first cache-hint policy — the
// read-once input stops occupying L2, leaving more capacity for dirty output
// lines so writebacks flush in larger same-direction batches (fewer HBM
// read<->write turnarounds, the identified limiter). (2) class-token reduction
// uses 4 independent accumulators to break its 113-deep serial add chain.

#define GRID15 15
#define NTOK   225
#define DIM    896
#define NGRP   366
#define CHUNK  64            // floats per chunk
#define CH4    (CHUNK / 4)   // 16 float4 per chunk
#define NCHUNK (DIM / CHUNK) // 14
#define TPB    512
#define TILE4  (NTOK * CH4)  // 3600 float4 = 57600 B
#define SMEM_BYTES (TILE4 * 16)

__device__ __forceinline__ float4 f4add(float4 a, float4 b) {
    return make_float4(a.x + b.x, a.y + b.y, a.z + b.z, a.w + b.w);
}
__device__ __forceinline__ float4 f4scale(float4 a, float s) {
    return make_float4(a.x * s, a.y * s, a.z * s, a.w * s);
}

__global__ __launch_bounds__(TPB) void clip_pool_kernel(
    const float* __restrict__ tok, float* __restrict__ out)
{
    extern __shared__ float4 s[];  // [225][16] float4

    const int b  = blockIdx.y;
    const int ch = blockIdx.x;
    const int ROW4 = DIM / 4;  // 224 float4 per token row in gmem

    // ---- stage token slice [225, 64 floats] via cp.async + evict_first ----
    const float4* g_tok = reinterpret_cast<const float4*>(
        tok + (size_t)b * NTOK * DIM + (size_t)ch * CHUNK);
    unsigned s_base = (unsigned)__cvta_generic_to_shared(s);

    unsigned long long pol;
    asm volatile("createpolicy.fractional.L2::evict_first.b64 %0, 1.0;"
                 : "=l"(pol));

    #pragma unroll
    for (int i = threadIdx.x; i < TILE4; i += TPB) {
        int t = i >> 4;            // token
        int c = i & 15;            // float4 within chunk
        unsigned dst = s_base + (unsigned)i * 16u;
        const float4* src = g_tok + t * ROW4 + c;
        asm volatile(
            "cp.async.cg.shared.global.L2::cache_hint [%0], [%1], 16, %2;\n"
            :: "r"(dst), "l"(src), "l"(pol));
    }
    asm volatile("cp.async.commit_group;\n" ::: "memory");
    asm volatile("cp.async.wait_group 0;\n" ::: "memory");
    __syncthreads();

    const int col  = threadIdx.x & 15;  // float4 lane within chunk (0..15)
    const int grow = threadIdx.x >> 4;  // task row (0..31)

    float4* g_out = reinterpret_cast<float4*>(
        out + (size_t)b * NGRP * DIM + (size_t)ch * CHUNK);

    if (grow < 13) {
        // ---- 3x3 windows, output row = grow ----
        const float4* r0 = s + ((grow    ) * GRID15) * CH4 + col;
        const float4* r1 = s + ((grow + 1) * GRID15) * CH4 + col;
        const float4* r2 = s + ((grow + 2) * GRID15) * CH4 + col;
        float4 v0 = f4add(f4add(r0[0 * CH4], r1[0 * CH4]), r2[0 * CH4]);
        float4 v1 = f4add(f4add(r0[1 * CH4], r1[1 * CH4]), r2[1 * CH4]);
        const float inv9 = 1.0f / 9.0f;
        #pragma unroll
        for (int c = 0; c < 13; c++) {
            float4 v2 = f4add(f4add(r0[(c + 2) * CH4], r1[(c + 2) * CH4]),
                              r2[(c + 2) * CH4]);
            float4 res = f4scale(f4add(f4add(v0, v1), v2), inv9);
            __stcs(&g_out[(size_t)(grow * 13 + c) * ROW4 + col], res);
            v0 = v1; v1 = v2;
        }
    } else if (grow < 27) {
        // ---- 2x2 windows, output row = grow - 13 ----
        const int rr = grow - 13;
        const float4* r0 = s + ((rr    ) * GRID15) * CH4 + col;
        const float4* r1 = s + ((rr + 1) * GRID15) * CH4 + col;
        float4 v0 = f4add(r0[0], r1[0]);
        #pragma unroll
        for (int c = 0; c < 14; c++) {
            float4 v1 = f4add(r0[(c + 1) * CH4], r1[(c + 1) * CH4]);
            float4 res = f4scale(f4add(v0, v1), 0.25f);
            __stcs(&g_out[(size_t)(169 + rr * 14 + c) * ROW4 + col], res);
            v0 = v1;
        }
    } else if (grow == 28 || grow == 29) {
        // ---- class token: warp 14's two lane-sets split 225 tokens;
        //      4 independent accumulators break the serial add chain;
        //      shfl_xor(16) combines across the half-warps. ----
        const int sub   = grow - 28;             // 0 or 1
        const int start = sub ? 113 : 0;
        const int end   = sub ? 225 : 113;
        float4 a0 = make_float4(0.f, 0.f, 0.f, 0.f);
        float4 a1 = a0, a2 = a0, a3 = a0;
        int t = start;
        for (; t + 3 < end; t += 4) {
            a0 = f4add(a0, s[(t    ) * CH4 + col]);
            a1 = f4add(a1, s[(t + 1) * CH4 + col]);
            a2 = f4add(a2, s[(t + 2) * CH4 + col]);
            a3 = f4add(a3, s[(t + 3) * CH4 + col]);
        }
        for (; t < end; t++) a0 = f4add(a0, s[t * CH4 + col]);
        float4 acc = f4add(f4add(a0, a1), f4add(a2, a3));
        acc.x += __shfl_xor_sync(0xffffffffu, acc.x, 16);
        acc.y += __shfl_xor_sync(0xffffffffu, acc.y, 16);
        acc.z += __shfl_xor_sync(0xffffffffu, acc.z, 16);
        acc.w += __shfl_xor_sync(0xffffffffu, acc.w, 16);
        if (sub == 0)
            __stcs(&g_out[(size_t)365 * ROW4 + col], f4scale(acc, 1.0f / 225.0f));
    }
    // grows 27, 30, 31: idle in phase 2 (helped with staging)
}

extern "C" void kernel_launch(void* const* d_in, const int* in_sizes, int n_in,
                              void* d_out, int out_size)
{
    (void)in_sizes; (void)n_in; (void)out_size;
    const float* tok = (const float*)d_in[0];
    // d_in[1]/d_in[2] (masks) are deterministic sliding-window tables,
    // reproduced arithmetically in-kernel.
    float* out = (float*)d_out;

    static bool attr_set = false;
    if (!attr_set) {
        cudaFuncSetAttribute(clip_pool_kernel,
                             cudaFuncAttributeMaxDynamicSharedMemorySize,
                             SMEM_BYTES);
        attr_set = true;
    }

    dim3 grid(NCHUNK, 512);
    clip_pool_kernel<<<grid, TPB, SMEM_BYTES>>>(tok, out);
}

// round 11
// speedup vs baseline: 1.0043x; 1.0043x over previous
#include <cuda_runtime.h>

// CLIP_AD pooling: patch_tokens [B=512, 225, D=896] f32 -> out [B, 366, 896]:
//   groups   0..168 : mean over 3x3 sliding windows on 15x15 grid (13x13)
//   groups 169..364 : mean over 2x2 sliding windows (14x14)
//   group      365  : mean over all 225 tokens
//
// FINAL (= R8, best measured 161.86us): non-persistent, one CTA per
// (batch, 64-float D-chunk). cp.async.cg stages the 225x64f token slice
// (57.6KB smem, 3 CTAs/SM); separable sliding-window sums (vertical column
// sums + rolling horizontal window in registers); __stcs streaming stores.
// Masks are deterministic sliding-window tables, reproduced arithmetically.
//
// Convergence note: LDG+STS / cp.async(16/32/64B-chunk shapes) / evict_first /
// persistent double-buffer all plateau at ~6.5TB/s (82% HBM) on the 1.083GB
// compulsory traffic — the path-independent LTS/HBM service cap, not an
// SM-side limit. This config is the fastest measured instance of that plateau.

#define GRID15 15
#define NTOK   225
#define DIM    896
#define NGRP   366
#define CHUNK  64            // floats per chunk
#define CH4    (CHUNK / 4)   // 16 float4 per chunk
#define NCHUNK (DIM / CHUNK) // 14
#define TPB    512
#define TILE4  (NTOK * CH4)  // 3600 float4 = 57600 B
#define SMEM_BYTES (TILE4 * 16)

__device__ __forceinline__ float4 f4add(float4 a, float4 b) {
    return make_float4(a.x + b.x, a.y + b.y, a.z + b.z, a.w + b.w);
}
__device__ __forceinline__ float4 f4scale(float4 a, float s) {
    return make_float4(a.x * s, a.y * s, a.z * s, a.w * s);
}

__global__ __launch_bounds__(TPB) void clip_pool_kernel(
    const float* __restrict__ tok, float* __restrict__ out)
{
    extern __shared__ float4 s[];  // [225][16] float4

    const int b  = blockIdx.y;
    const int ch = blockIdx.x;
    const int ROW4 = DIM / 4;  // 224 float4 per token row in gmem

    // ---- stage token slice [225, 64 floats] into smem via cp.async ----
    const float4* g_tok = reinterpret_cast<const float4*>(
        tok + (size_t)b * NTOK * DIM + (size_t)ch * CHUNK);
    unsigned s_base = (unsigned)__cvta_generic_to_shared(s);

    #pragma unroll
    for (int i = threadIdx.x; i < TILE4; i += TPB) {
        int t = i >> 4;            // token
        int c = i & 15;            // float4 within chunk
        unsigned dst = s_base + (unsigned)i * 16u;
        const float4* src = g_tok + t * ROW4 + c;
        asm volatile("cp.async.cg.shared.global [%0], [%1], 16;\n"
                     :: "r"(dst), "l"(src));
    }
    asm volatile("cp.async.commit_group;\n" ::: "memory");
    asm volatile("cp.async.wait_group 0;\n" ::: "memory");
    __syncthreads();

    const int col  = threadIdx.x & 15;  // float4 lane within chunk (0..15)
    const int grow = threadIdx.x >> 4;  // task row (0..31)

    float4* g_out = reinterpret_cast<float4*>(
        out + (size_t)b * NGRP * DIM + (size_t)ch * CHUNK);

    if (grow < 13) {
        // ---- 3x3 windows, output row = grow ----
        const float4* r0 = s + ((grow    ) * GRID15) * CH4 + col;
        const float4* r1 = s + ((grow + 1) * GRID15) * CH4 + col;
        const float4* r2 = s + ((grow + 2) * GRID15) * CH4 + col;
        float4 v0 = f4add(f4add(r0[0 * CH4], r1[0 * CH4]), r2[0 * CH4]);
        float4 v1 = f4add(f4add(r0[1 * CH4], r1[1 * CH4]), r2[1 * CH4]);
        const float inv9 = 1.0f / 9.0f;
        #pragma unroll
        for (int c = 0; c < 13; c++) {
            float4 v2 = f4add(f4add(r0[(c + 2) * CH4], r1[(c + 2) * CH4]),
                              r2[(c + 2) * CH4]);
            float4 res = f4scale(f4add(f4add(v0, v1), v2), inv9);
            __stcs(&g_out[(size_t)(grow * 13 + c) * ROW4 + col], res);
            v0 = v1; v1 = v2;
        }
    } else if (grow < 27) {
        // ---- 2x2 windows, output row = grow - 13 ----
        const int rr = grow - 13;
        const float4* r0 = s + ((rr    ) * GRID15) * CH4 + col;
        const float4* r1 = s + ((rr + 1) * GRID15) * CH4 + col;
        float4 v0 = f4add(r0[0], r1[0]);
        #pragma unroll
        for (int c = 0; c < 14; c++) {
            float4 v1 = f4add(r0[(c + 1) * CH4], r1[(c + 1) * CH4]);
            float4 res = f4scale(f4add(v0, v1), 0.25f);
            __stcs(&g_out[(size_t)(169 + rr * 14 + c) * ROW4 + col], res);
            v0 = v1;
        }
    } else if (grow == 28 || grow == 29) {
        // ---- class token: warp 14's two lane-sets split 225 tokens,
        //      shfl_xor(16) combines across the half-warps. ----
        const int sub   = grow - 28;             // 0 or 1
        const int start = sub ? 113 : 0;
        const int end   = sub ? 225 : 113;
        float4 acc = make_float4(0.f, 0.f, 0.f, 0.f);
        for (int t = start; t < end; t++) {
            float4 v = s[t * CH4 + col];
            acc.x += v.x; acc.y += v.y; acc.z += v.z; acc.w += v.w;
        }
        acc.x += __shfl_xor_sync(0xffffffffu, acc.x, 16);
        acc.y += __shfl_xor_sync(0xffffffffu, acc.y, 16);
        acc.z += __shfl_xor_sync(0xffffffffu, acc.z, 16);
        acc.w += __shfl_xor_sync(0xffffffffu, acc.w, 16);
        if (sub == 0)
            __stcs(&g_out[(size_t)365 * ROW4 + col], f4scale(acc, 1.0f / 225.0f));
    }
    // grows 27, 30, 31: idle in phase 2 (helped with staging)
}

extern "C" void kernel_launch(void* const* d_in, const int* in_sizes, int n_in,
                              void* d_out, int out_size)
{
    (void)in_sizes; (void)n_in; (void)out_size;
    const float* tok = (const float*)d_in[0];
    // d_in[1]/d_in[2] (masks) are deterministic sliding-window tables,
    // reproduced arithmetically in-kernel.
    float* out = (float*)d_out;

    static bool attr_set = false;
    if (!attr_set) {
        cudaFuncSetAttribute(clip_pool_kernel,
                             cudaFuncAttributeMaxDynamicSharedMemorySize,
                             SMEM_BYTES);
        attr_set = true;
    }

    dim3 grid(NCHUNK, 512);
    clip_pool_kernel<<<grid, TPB, SMEM_BYTES>>>(tok, out);
}

// round 12
// speedup vs baseline: 1.0117x; 1.0073x over previous
#include <cuda_runtime.h>

// CLIP_AD pooling: patch_tokens [B=512, 225, D=896] f32 -> out [B, 366, 896]:
//   groups   0..168 : mean over 3x3 sliding windows on 15x15 grid (13x13)
//   groups 169..364 : mean over 2x2 sliding windows (14x14)
//   group      365  : mean over all 225 tokens
//
// FINAL (best measured 161.86us; re-run 163.2 — run variance ±1.5us):
// non-persistent, one CTA per (batch, 64-float D-chunk). cp.async.cg stages
// the 225x64f token slice (57.6KB smem, 3 CTAs/SM); separable sliding-window
// sums (vertical column sums + rolling horizontal window in registers);
// __stcs streaming stores. Masks are deterministic sliding-window tables,
// reproduced arithmetically — the int32 mask inputs are never read.
//
// Convergence: LDG+STS / cp.async(16/32/64B shapes) / evict_first /
// persistent double-buffer / forced-occupancy variants all plateau at
// 6.45-6.56 TB/s on 1.083GB compulsory traffic — the path-independent
// LTS/HBM service cap for this mixed 38%R/62%W stream. Occupancy swept
// 35-73% with no effect on DRAM%, confirming the limiter is below the SMs.

#define GRID15 15
#define NTOK   225
#define DIM    896
#define NGRP   366
#define CHUNK  64            // floats per chunk
#define CH4    (CHUNK / 4)   // 16 float4 per chunk
#define NCHUNK (DIM / CHUNK) // 14
#define TPB    512
#define TILE4  (NTOK * CH4)  // 3600 float4 = 57600 B
#define SMEM_BYTES (TILE4 * 16)

__device__ __forceinline__ float4 f4add(float4 a, float4 b) {
    return make_float4(a.x + b.x, a.y + b.y, a.z + b.z, a.w + b.w);
}
__device__ __forceinline__ float4 f4scale(float4 a, float s) {
    return make_float4(a.x * s, a.y * s, a.z * s, a.w * s);
}

__global__ __launch_bounds__(TPB) void clip_pool_kernel(
    const float* __restrict__ tok, float* __restrict__ out)
{
    extern __shared__ float4 s[];  // [225][16] float4

    const int b  = blockIdx.y;
    const int ch = blockIdx.x;
    const int ROW4 = DIM / 4;  // 224 float4 per token row in gmem

    // ---- stage token slice [225, 64 floats] into smem via cp.async ----
    const float4* g_tok = reinterpret_cast<const float4*>(
        tok + (size_t)b * NTOK * DIM + (size_t)ch * CHUNK);
    unsigned s_base = (unsigned)__cvta_generic_to_shared(s);

    #pragma unroll
    for (int i = threadIdx.x; i < TILE4; i += TPB) {
        int t = i >> 4;            // token
        int c = i & 15;            // float4 within chunk
        unsigned dst = s_base + (unsigned)i * 16u;
        const float4* src = g_tok + t * ROW4 + c;
        asm volatile("cp.async.cg.shared.global [%0], [%1], 16;\n"
                     :: "r"(dst), "l"(src));
    }
    asm volatile("cp.async.commit_group;\n" ::: "memory");
    asm volatile("cp.async.wait_group 0;\n" ::: "memory");
    __syncthreads();

    const int col  = threadIdx.x & 15;  // float4 lane within chunk (0..15)
    const int grow = threadIdx.x >> 4;  // task row (0..31)

    float4* g_out = reinterpret_cast<float4*>(
        out + (size_t)b * NGRP * DIM + (size_t)ch * CHUNK);

    if (grow < 13) {
        // ---- 3x3 windows, output row = grow ----
        const float4* r0 = s + ((grow    ) * GRID15) * CH4 + col;
        const float4* r1 = s + ((grow + 1) * GRID15) * CH4 + col;
        const float4* r2 = s + ((grow + 2) * GRID15) * CH4 + col;
        float4 v0 = f4add(f4add(r0[0 * CH4], r1[0 * CH4]), r2[0 * CH4]);
        float4 v1 = f4add(f4add(r0[1 * CH4], r1[1 * CH4]), r2[1 * CH4]);
        const float inv9 = 1.0f / 9.0f;
        #pragma unroll
        for (int c = 0; c < 13; c++) {
            float4 v2 = f4add(f4add(r0[(c + 2) * CH4], r1[(c + 2) * CH4]),
                              r2[(c + 2) * CH4]);
            float4 res = f4scale(f4add(f4add(v0, v1), v2), inv9);
            __stcs(&g_out[(size_t)(grow * 13 + c) * ROW4 + col], res);
            v0 = v1; v1 = v2;
        }
    } else if (grow < 27) {
        // ---- 2x2 windows, output row = grow - 13 ----
        const int rr = grow - 13;
        const float4* r0 = s + ((rr    ) * GRID15) * CH4 + col;
        const float4* r1 = s + ((rr + 1) * GRID15) * CH4 + col;
        float4 v0 = f4add(r0[0], r1[0]);
        #pragma unroll
        for (int c = 0; c < 14; c++) {
            float4 v1 = f4add(r0[(c + 1) * CH4], r1[(c + 1) * CH4]);
            float4 res = f4scale(f4add(v0, v1), 0.25f);
            __stcs(&g_out[(size_t)(169 + rr * 14 + c) * ROW4 + col], res);
            v0 = v1;
        }
    } else if (grow == 28 || grow == 29) {
        // ---- class token: warp 14's two lane-sets split 225 tokens,
        //      shfl_xor(16) combines across the half-warps. ----
        const int sub   = grow - 28;             // 0 or 1
        const int start = sub ? 113 : 0;
        const int end   = sub ? 225 : 113;
        float4 acc = make_float4(0.f, 0.f, 0.f, 0.f);
        for (int t = start; t < end; t++) {
            float4 v = s[t * CH4 + col];
            acc.x += v.x; acc.y += v.y; acc.z += v.z; acc.w += v.w;
        }
        acc.x += __shfl_xor_sync(0xffffffffu, acc.x, 16);
        acc.y += __shfl_xor_sync(0xffffffffu, acc.y, 16);
        acc.z += __shfl_xor_sync(0xffffffffu, acc.z, 16);
        acc.w += __shfl_xor_sync(0xffffffffu, acc.w, 16);
        if (sub == 0)
            __stcs(&g_out[(size_t)365 * ROW4 + col], f4scale(acc, 1.0f / 225.0f));
    }
    // grows 27, 30, 31: idle in phase 2 (helped with staging)
}

extern "C" void kernel_launch(void* const* d_in, const int* in_sizes, int n_in,
                              void* d_out, int out_size)
{
    (void)in_sizes; (void)n_in; (void)out_size;
    const float* tok = (const float*)d_in[0];
    // d_in[1]/d_in[2] (masks) are deterministic sliding-window tables,
    // reproduced arithmetically in-kernel.
    float* out = (float*)d_out;

    static bool attr_set = false;
    if (!attr_set) {
        cudaFuncSetAttribute(clip_pool_kernel,
                             cudaFuncAttributeMaxDynamicSharedMemorySize,
                             SMEM_BYTES);
        attr_set = true;
    }

    dim3 grid(NCHUNK, 512);
    clip_pool_kernel<<<grid, TPB, SMEM_BYTES>>>(tok, out);
}

// round 13
// speedup vs baseline: 1.0125x; 1.0008x over previous
#include <cuda_runtime.h>

// CLIP_AD pooling: patch_tokens [B=512, 225, D=896] f32 -> out [B, 366, 896]:
//   groups   0..168 : mean over 3x3 sliding windows on 15x15 grid (13x13)
//   groups 169..364 : mean over 2x2 sliding windows (14x14)
//   group      365  : mean over all 225 tokens
//
// R12: R8 base (CHUNK=64, TPB=512, cp.async, __stcs; plateau 161.9-163.2us).
// Change: two-commit-group split staging. Group A = tokens 0..134 (grid rows
// 0..8), group B = rest. After wait_group 1 (A done), compute every output
// depending only on rows <=8 (3x3 rows 0..6, 2x2 rows 0..7); after
// wait_group 0, the remainder + class token. Same DRAM traffic; shortens the
// per-CTA critical path ~2-3us, which is what the launch-ramp and final
// partial wave (64 of 7168 CTAs) are bound by.

#define GRID15 15
#define NTOK   225
#define DIM    896
#define NGRP   366
#define CHUNK  64            // floats per chunk
#define CH4    (CHUNK / 4)   // 16 float4 per chunk
#define NCHUNK (DIM / CHUNK) // 14
#define TPB    512
#define TILE4  (NTOK * CH4)  // 3600 float4 = 57600 B
#define SPLITT 135           // tokens 0..134 = grid rows 0..8
#define SPLIT4 (SPLITT * CH4)
#define SMEM_BYTES (TILE4 * 16)

__device__ __forceinline__ float4 f4add(float4 a, float4 b) {
    return make_float4(a.x + b.x, a.y + b.y, a.z + b.z, a.w + b.w);
}
__device__ __forceinline__ float4 f4scale(float4 a, float s) {
    return make_float4(a.x * s, a.y * s, a.z * s, a.w * s);
}

__global__ __launch_bounds__(TPB) void clip_pool_kernel(
    const float* __restrict__ tok, float* __restrict__ out)
{
    extern __shared__ float4 s[];  // [225][16] float4

    const int b  = blockIdx.y;
    const int ch = blockIdx.x;
    const int ROW4 = DIM / 4;  // 224 float4 per token row in gmem

    const float4* g_tok = reinterpret_cast<const float4*>(
        tok + (size_t)b * NTOK * DIM + (size_t)ch * CHUNK);
    unsigned s_base = (unsigned)__cvta_generic_to_shared(s);

    // ---- group A: tokens 0..134 ----
    #pragma unroll
    for (int i = threadIdx.x; i < SPLIT4; i += TPB) {
        int t = i >> 4;
        int c = i & 15;
        asm volatile("cp.async.cg.shared.global [%0], [%1], 16;\n"
                     :: "r"(s_base + (unsigned)i * 16u),
                        "l"(g_tok + t * ROW4 + c));
    }
    asm volatile("cp.async.commit_group;\n" ::: "memory");

    // ---- group B: tokens 135..224 ----
    #pragma unroll
    for (int i = SPLIT4 + threadIdx.x; i < TILE4; i += TPB) {
        int t = i >> 4;
        int c = i & 15;
        asm volatile("cp.async.cg.shared.global [%0], [%1], 16;\n"
                     :: "r"(s_base + (unsigned)i * 16u),
                        "l"(g_tok + t * ROW4 + c));
    }
    asm volatile("cp.async.commit_group;\n" ::: "memory");

    const int col  = threadIdx.x & 15;  // float4 lane within chunk (0..15)
    const int grow = threadIdx.x >> 4;  // task row (0..31)

    float4* g_out = reinterpret_cast<float4*>(
        out + (size_t)b * NGRP * DIM + (size_t)ch * CHUNK);

    const float inv9 = 1.0f / 9.0f;

    // ================= phase 1: outputs needing grid rows 0..8 =============
    asm volatile("cp.async.wait_group 1;\n" ::: "memory");
    __syncthreads();

    if (grow < 7) {
        // ---- 3x3 windows, output rows 0..6 (need grid rows <= 8) ----
        const float4* r0 = s + ((grow    ) * GRID15) * CH4 + col;
        const float4* r1 = s + ((grow + 1) * GRID15) * CH4 + col;
        const float4* r2 = s + ((grow + 2) * GRID15) * CH4 + col;
        float4 v0 = f4add(f4add(r0[0 * CH4], r1[0 * CH4]), r2[0 * CH4]);
        float4 v1 = f4add(f4add(r0[1 * CH4], r1[1 * CH4]), r2[1 * CH4]);
        #pragma unroll
        for (int c = 0; c < 13; c++) {
            float4 v2 = f4add(f4add(r0[(c + 2) * CH4], r1[(c + 2) * CH4]),
                              r2[(c + 2) * CH4]);
            float4 res = f4scale(f4add(f4add(v0, v1), v2), inv9);
            __stcs(&g_out[(size_t)(grow * 13 + c) * ROW4 + col], res);
            v0 = v1; v1 = v2;
        }
    } else if (grow >= 13 && grow < 21) {
        // ---- 2x2 windows, output rows 0..7 (need grid rows <= 8) ----
        const int rr = grow - 13;
        const float4* r0 = s + ((rr    ) * GRID15) * CH4 + col;
        const float4* r1 = s + ((rr + 1) * GRID15) * CH4 + col;
        float4 v0 = f4add(r0[0], r1[0]);
        #pragma unroll
        for (int c = 0; c < 14; c++) {
            float4 v1 = f4add(r0[(c + 1) * CH4], r1[(c + 1) * CH4]);
            float4 res = f4scale(f4add(v0, v1), 0.25f);
            __stcs(&g_out[(size_t)(169 + rr * 14 + c) * ROW4 + col], res);
            v0 = v1;
        }
    }

    // ================= phase 2: remainder (needs all tokens) ===============
    asm volatile("cp.async.wait_group 0;\n" ::: "memory");
    __syncthreads();

    if (grow >= 7 && grow < 13) {
        // ---- 3x3 windows, output rows 7..12 ----
        const float4* r0 = s + ((grow    ) * GRID15) * CH4 + col;
        const float4* r1 = s + ((grow + 1) * GRID15) * CH4 + col;
        const float4* r2 = s + ((grow + 2) * GRID15) * CH4 + col;
        float4 v0 = f4add(f4add(r0[0 * CH4], r1[0 * CH4]), r2[0 * CH4]);
        float4 v1 = f4add(f4add(r0[1 * CH4], r1[1 * CH4]), r2[1 * CH4]);
        #pragma unroll
        for (int c = 0; c < 13; c++) {
            float4 v2 = f4add(f4add(r0[(c + 2) * CH4], r1[(c + 2) * CH4]),
                              r2[(c + 2) * CH4]);
            float4 res = f4scale(f4add(f4add(v0, v1), v2), inv9);
            __stcs(&g_out[(size_t)(grow * 13 + c) * ROW4 + col], res);
            v0 = v1; v1 = v2;
        }
    } else if (grow >= 21 && grow < 27) {
        // ---- 2x2 windows, output rows 8..13 ----
        const int rr = grow - 13;
        const float4* r0 = s + ((rr    ) * GRID15) * CH4 + col;
        const float4* r1 = s + ((rr + 1) * GRID15) * CH4 + col;
        float4 v0 = f4add(r0[0], r1[0]);
        #pragma unroll
        for (int c = 0; c < 14; c++) {
            float4 v1 = f4add(r0[(c + 1) * CH4], r1[(c + 1) * CH4]);
            float4 res = f4scale(f4add(v0, v1), 0.25f);
            __stcs(&g_out[(size_t)(169 + rr * 14 + c) * ROW4 + col], res);
            v0 = v1;
        }
    } else if (grow == 28 || grow == 29) {
        // ---- class token: two lane-sets split 225 tokens, shfl(16) ----
        const int sub   = grow - 28;
        const int start = sub ? 113 : 0;
        const int end   = sub ? 225 : 113;
        float4 acc = make_float4(0.f, 0.f, 0.f, 0.f);
        for (int t = start; t < end; t++) {
            float4 v = s[t * CH4 + col];
            acc.x += v.x; acc.y += v.y; acc.z += v.z; acc.w += v.w;
        }
        acc.x += __shfl_xor_sync(0xffffffffu, acc.x, 16);
        acc.y += __shfl_xor_sync(0xffffffffu, acc.y, 16);
        acc.z += __shfl_xor_sync(0xffffffffu, acc.z, 16);
        acc.w += __shfl_xor_sync(0xffffffffu, acc.w, 16);
        if (sub == 0)
            __stcs(&g_out[(size_t)365 * ROW4 + col], f4scale(acc, 1.0f / 225.0f));
    }
}

extern "C" void kernel_launch(void* const* d_in, const int* in_sizes, int n_in,
                              void* d_out, int out_size)
{
    (void)in_sizes; (void)n_in; (void)out_size;
    const float* tok = (const float*)d_in[0];
    // d_in[1]/d_in[2] (masks) are deterministic sliding-window tables,
    // reproduced arithmetically in-kernel.
    float* out = (float*)d_out;

    static bool attr_set = false;
    if (!attr_set) {
        cudaFuncSetAttribute(clip_pool_kernel,
                             cudaFuncAttributeMaxDynamicSharedMemorySize,
                             SMEM_BYTES);
        attr_set = true;
    }

    dim3 grid(NCHUNK, 512);
    clip_pool_kernel<<<grid, TPB, SMEM_BYTES>>>(tok, out);
}